// round 1
// baseline (speedup 1.0000x reference)
#include <cuda_runtime.h>
#include <math.h>

constexpr int NSEQ = 384;         // N
constexpr int CIN  = 128;         // C_IN
constexpr int NH   = 4;           // heads
constexpr int CHD  = 32;          // head dim
constexpr int NTOK = NSEQ * NSEQ; // 147456
constexpr float QSCALE = 0.17677669529663687f; // 1/sqrt(32)

// ---- scratch (device globals; allocation APIs are forbidden) ----
__device__ float g_zn[NTOK * CIN];
__device__ float g_q [NTOK * CIN];
__device__ float g_k [NTOK * CIN];
__device__ float g_v [NTOK * CIN];
__device__ float g_g [NTOK * CIN];
__device__ float g_og[NTOK * CIN];
__device__ float g_tri[NH * NTOK];   // [h][i][j]

// ============================================================
// Kernel 1: LayerNorm + tri bias. One block per token, 128 thr.
// ============================================================
__global__ void ln_tri_kernel(const float* __restrict__ z,
                              const float* __restrict__ ln_w,
                              const float* __restrict__ ln_b,
                              const float* __restrict__ w_tri) {
    int t = blockIdx.x;          // token = i*NSEQ + j
    int c = threadIdx.x;         // channel
    int lane = c & 31, warp = c >> 5;

    float x = z[t * CIN + c];
    float v1 = x, v2 = x * x;
    #pragma unroll
    for (int off = 16; off; off >>= 1) {
        v1 += __shfl_xor_sync(~0u, v1, off);
        v2 += __shfl_xor_sync(~0u, v2, off);
    }
    __shared__ float s1[4], s2[4];
    if (lane == 0) { s1[warp] = v1; s2[warp] = v2; }
    __syncthreads();
    float mean = (s1[0] + s1[1] + s1[2] + s1[3]) * (1.0f / CIN);
    float msq  = (s2[0] + s2[1] + s2[2] + s2[3]) * (1.0f / CIN);
    float var  = msq - mean * mean;
    float zn   = (x - mean) * rsqrtf(var + 1e-5f) * ln_w[c] + ln_b[c];
    g_zn[t * CIN + c] = zn;

    // tri[h] = sum_c zn_c * w_tri[c][h]
    __shared__ float sh[4][4];   // [warp][h]
    float p[4];
    #pragma unroll
    for (int h = 0; h < 4; h++) p[h] = zn * w_tri[c * NH + h];
    #pragma unroll
    for (int off = 16; off; off >>= 1)
        #pragma unroll
        for (int h = 0; h < 4; h++) p[h] += __shfl_xor_sync(~0u, p[h], off);
    if (lane == 0)
        #pragma unroll
        for (int h = 0; h < 4; h++) sh[warp][h] = p[h];
    __syncthreads();
    if (c < 4)   // c == h
        g_tri[c * NTOK + t] = sh[0][c] + sh[1][c] + sh[2][c] + sh[3][c];
}

// ============================================================
// Kernel 2: projections  zn[NTOK,128] @ [wq|wk|wv|wg][128,512]
// BM=64, BN=64, BK=32, 256 threads, 4x4 microtile.
// ============================================================
constexpr int BM = 64, BN = 64, BK = 32;

__global__ void proj_kernel(const float* __restrict__ wq,
                            const float* __restrict__ wk,
                            const float* __restrict__ wv,
                            const float* __restrict__ wg) {
    __shared__ float As[BM][BK + 1];
    __shared__ float Bs[BK][BN + 1];
    int tid = threadIdx.x;
    int tx = tid & 15, ty = tid >> 4;
    int m0 = blockIdx.y * BM;
    int n0 = blockIdx.x * BN;           // 0..511 in steps of 64
    int sel = n0 >> 7;                  // tile fully inside one weight matrix
    const float* W = (sel == 0) ? wq : (sel == 1) ? wk : (sel == 2) ? wv : wg;
    int ncol0 = n0 & 127;

    float acc[4][4] = {};
    for (int k0 = 0; k0 < CIN; k0 += BK) {
        #pragma unroll
        for (int e = 0; e < 8; e++) {
            int l = tid + 256 * e;
            As[l >> 5][l & 31] = g_zn[(m0 + (l >> 5)) * CIN + k0 + (l & 31)];
        }
        #pragma unroll
        for (int e = 0; e < 8; e++) {
            int l = tid + 256 * e;
            Bs[l >> 6][l & 63] = W[(k0 + (l >> 6)) * CIN + ncol0 + (l & 63)];
        }
        __syncthreads();
        #pragma unroll
        for (int kk = 0; kk < BK; kk++) {
            float ra[4], rb[4];
            #pragma unroll
            for (int ii = 0; ii < 4; ii++) ra[ii] = As[ty * 4 + ii][kk];
            #pragma unroll
            for (int jj = 0; jj < 4; jj++) rb[jj] = Bs[kk][tx * 4 + jj];
            #pragma unroll
            for (int ii = 0; ii < 4; ii++)
                #pragma unroll
                for (int jj = 0; jj < 4; jj++)
                    acc[ii][jj] += ra[ii] * rb[jj];
        }
        __syncthreads();
    }
    #pragma unroll
    for (int ii = 0; ii < 4; ii++)
        #pragma unroll
        for (int jj = 0; jj < 4; jj++) {
            int gm  = m0 + ty * 4 + ii;
            int lc  = ncol0 + tx * 4 + jj;   // 0..127 within matrix
            int idx = gm * CIN + lc;
            float val = acc[ii][jj];
            if      (sel == 0) g_q[idx] = val * QSCALE;
            else if (sel == 1) g_k[idx] = val;
            else if (sel == 2) g_v[idx] = val;
            else               g_g[idx] = 1.0f / (1.0f + __expf(-val));
        }
}

// ============================================================
// Kernel 3: attention per (i, h). Block = 128 threads (4 warps),
// K/V tiles smem-resident (stride 33 to avoid bank conflicts).
// ============================================================
__global__ void attn_kernel(const float* __restrict__ mask) {
    int i = blockIdx.x, h = blockIdx.y;
    extern __shared__ float sm[];
    float* Ks = sm;                       // 384*33
    float* Vs = Ks + NSEQ * 33;           // 384*33
    float* ps = Vs + NSEQ * 33;           // 4*384
    float* qs = ps + 4 * NSEQ;            // 4*32
    float* bs = qs + 4 * 32;              // 384

    int tid = threadIdx.x, warp = tid >> 5, lane = tid & 31;

    for (int l = tid; l < NSEQ * CHD; l += 128) {
        int k = l >> 5, c = l & 31;
        int gidx = ((i * NSEQ + k) * NH + h) * CHD + c;
        Ks[k * 33 + c] = g_k[gidx];
        Vs[k * 33 + c] = g_v[gidx];
    }
    for (int k = tid; k < NSEQ; k += 128)
        bs[k] = 1e9f * (mask[i * NSEQ + k] - 1.0f);
    __syncthreads();

    const float* trih = g_tri + h * NTOK;

    for (int q = warp; q < NSEQ; q += 4) {
        qs[warp * 32 + lane] = g_q[((i * NSEQ + q) * NH + h) * CHD + lane];
        __syncwarp();

        float s[12];
        float mx = -1e30f;
        #pragma unroll
        for (int kk = 0; kk < 12; kk++) {
            int k = lane + kk * 32;
            float a0 = 0.f, a1 = 0.f, a2 = 0.f, a3 = 0.f;
            #pragma unroll
            for (int c = 0; c < 32; c += 4) {
                a0 += qs[warp * 32 + c + 0] * Ks[k * 33 + c + 0];
                a1 += qs[warp * 32 + c + 1] * Ks[k * 33 + c + 1];
                a2 += qs[warp * 32 + c + 2] * Ks[k * 33 + c + 2];
                a3 += qs[warp * 32 + c + 3] * Ks[k * 33 + c + 3];
            }
            float sc = (a0 + a1) + (a2 + a3) + bs[k] + trih[q * NSEQ + k];
            s[kk] = sc;
            mx = fmaxf(mx, sc);
        }
        #pragma unroll
        for (int off = 16; off; off >>= 1)
            mx = fmaxf(mx, __shfl_xor_sync(~0u, mx, off));
        float sum = 0.f;
        #pragma unroll
        for (int kk = 0; kk < 12; kk++) { s[kk] = __expf(s[kk] - mx); sum += s[kk]; }
        #pragma unroll
        for (int off = 16; off; off >>= 1)
            sum += __shfl_xor_sync(~0u, sum, off);
        float inv = 1.0f / sum;
        #pragma unroll
        for (int kk = 0; kk < 12; kk++)
            ps[warp * NSEQ + lane + kk * 32] = s[kk] * inv;
        __syncwarp();

        float o0 = 0.f, o1 = 0.f, o2 = 0.f, o3 = 0.f;
        #pragma unroll 8
        for (int k = 0; k < NSEQ; k += 4) {
            o0 += ps[warp * NSEQ + k + 0] * Vs[(k + 0) * 33 + lane];
            o1 += ps[warp * NSEQ + k + 1] * Vs[(k + 1) * 33 + lane];
            o2 += ps[warp * NSEQ + k + 2] * Vs[(k + 2) * 33 + lane];
            o3 += ps[warp * NSEQ + k + 3] * Vs[(k + 3) * 33 + lane];
        }
        float o = (o0 + o1) + (o2 + o3);
        int idx = ((i * NSEQ + q) * NH + h) * CHD + lane;
        g_og[idx] = o * g_g[idx];
        __syncwarp();
    }
}

// ============================================================
// Kernel 4: out = og[NTOK,128] @ wo[128,128]
// ============================================================
__global__ void out_kernel(const float* __restrict__ wo,
                           float* __restrict__ out) {
    __shared__ float As[BM][BK + 1];
    __shared__ float Bs[BK][BN + 1];
    int tid = threadIdx.x;
    int tx = tid & 15, ty = tid >> 4;
    int m0 = blockIdx.y * BM;
    int n0 = blockIdx.x * BN;

    float acc[4][4] = {};
    for (int k0 = 0; k0 < CIN; k0 += BK) {
        #pragma unroll
        for (int e = 0; e < 8; e++) {
            int l = tid + 256 * e;
            As[l >> 5][l & 31] = g_og[(m0 + (l >> 5)) * CIN + k0 + (l & 31)];
        }
        #pragma unroll
        for (int e = 0; e < 8; e++) {
            int l = tid + 256 * e;
            Bs[l >> 6][l & 63] = wo[(k0 + (l >> 6)) * CIN + n0 + (l & 63)];
        }
        __syncthreads();
        #pragma unroll
        for (int kk = 0; kk < BK; kk++) {
            float ra[4], rb[4];
            #pragma unroll
            for (int ii = 0; ii < 4; ii++) ra[ii] = As[ty * 4 + ii][kk];
            #pragma unroll
            for (int jj = 0; jj < 4; jj++) rb[jj] = Bs[kk][tx * 4 + jj];
            #pragma unroll
            for (int ii = 0; ii < 4; ii++)
                #pragma unroll
                for (int jj = 0; jj < 4; jj++)
                    acc[ii][jj] += ra[ii] * rb[jj];
        }
        __syncthreads();
    }
    #pragma unroll
    for (int ii = 0; ii < 4; ii++)
        #pragma unroll
        for (int jj = 0; jj < 4; jj++)
            out[(m0 + ty * 4 + ii) * CIN + n0 + tx * 4 + jj] = acc[ii][jj];
}

// ============================================================
extern "C" void kernel_launch(void* const* d_in, const int* in_sizes, int n_in,
                              void* d_out, int out_size) {
    const float* z     = (const float*)d_in[0];
    const float* mask  = (const float*)d_in[1];
    const float* ln_w  = (const float*)d_in[2];
    const float* ln_b  = (const float*)d_in[3];
    const float* w_tri = (const float*)d_in[4];
    const float* wq    = (const float*)d_in[5];
    const float* wk    = (const float*)d_in[6];
    const float* wv    = (const float*)d_in[7];
    const float* wg    = (const float*)d_in[8];
    const float* wo    = (const float*)d_in[9];
    float* out = (float*)d_out;

    ln_tri_kernel<<<NTOK, 128>>>(z, ln_w, ln_b, w_tri);

    dim3 gp(512 / BN, NTOK / BM);
    proj_kernel<<<gp, 256>>>(wq, wk, wv, wg);

    size_t smem = (size_t)(2 * NSEQ * 33 + 4 * NSEQ + 4 * 32 + NSEQ) * sizeof(float);
    cudaFuncSetAttribute(attn_kernel, cudaFuncAttributeMaxDynamicSharedMemorySize, (int)smem);
    dim3 ga(NSEQ, NH);
    attn_kernel<<<ga, 128, smem>>>(mask);

    dim3 go(CIN / BN, NTOK / BM);
    out_kernel<<<go, 256>>>(wo, out);
}

// round 2
// speedup vs baseline: 1.6136x; 1.6136x over previous
#include <cuda_runtime.h>
#include <math.h>

constexpr int NSEQ = 384;         // N
constexpr int CIN  = 128;         // C_IN
constexpr int NH   = 4;           // heads
constexpr int CHD  = 32;          // head dim
constexpr int NTOK = NSEQ * NSEQ; // 147456
constexpr float QSCALE = 0.17677669529663687f; // 1/sqrt(32)

// ---- scratch (device globals; allocation APIs are forbidden) ----
__device__ float g_zn[NTOK * CIN];
__device__ float g_q [NTOK * CIN];
__device__ float g_k [NTOK * CIN];
__device__ float g_v [NTOK * CIN];
__device__ float g_g [NTOK * CIN];
__device__ float g_og[NTOK * CIN];
__device__ float g_tri[NH * NTOK];   // [h][i][j]

// ============================================================
// Kernel 1: LayerNorm + tri bias. One block per token, 128 thr.
// ============================================================
__global__ void ln_tri_kernel(const float* __restrict__ z,
                              const float* __restrict__ ln_w,
                              const float* __restrict__ ln_b,
                              const float* __restrict__ w_tri) {
    int t = blockIdx.x;          // token = i*NSEQ + j
    int c = threadIdx.x;         // channel
    int lane = c & 31, warp = c >> 5;

    float x = z[t * CIN + c];
    float v1 = x, v2 = x * x;
    #pragma unroll
    for (int off = 16; off; off >>= 1) {
        v1 += __shfl_xor_sync(~0u, v1, off);
        v2 += __shfl_xor_sync(~0u, v2, off);
    }
    __shared__ float s1[4], s2[4];
    if (lane == 0) { s1[warp] = v1; s2[warp] = v2; }
    __syncthreads();
    float mean = (s1[0] + s1[1] + s1[2] + s1[3]) * (1.0f / CIN);
    float msq  = (s2[0] + s2[1] + s2[2] + s2[3]) * (1.0f / CIN);
    float var  = msq - mean * mean;
    float zn   = (x - mean) * rsqrtf(var + 1e-5f) * ln_w[c] + ln_b[c];
    g_zn[t * CIN + c] = zn;

    // tri[h] = sum_c zn_c * w_tri[c][h]
    __shared__ float sh[4][4];   // [warp][h]
    float p[4];
    #pragma unroll
    for (int h = 0; h < 4; h++) p[h] = zn * w_tri[c * NH + h];
    #pragma unroll
    for (int off = 16; off; off >>= 1)
        #pragma unroll
        for (int h = 0; h < 4; h++) p[h] += __shfl_xor_sync(~0u, p[h], off);
    if (lane == 0)
        #pragma unroll
        for (int h = 0; h < 4; h++) sh[warp][h] = p[h];
    __syncthreads();
    if (c < 4)   // c == h
        g_tri[c * NTOK + t] = sh[0][c] + sh[1][c] + sh[2][c] + sh[3][c];
}

// ============================================================
// Kernel 2: projections  zn[NTOK,128] @ [wq|wk|wv|wg][128,512]
// BM=64, BN=64, BK=32, 256 threads, 4x4 microtile.
// ============================================================
constexpr int BM = 64, BN = 64, BK = 32;

__global__ void proj_kernel(const float* __restrict__ wq,
                            const float* __restrict__ wk,
                            const float* __restrict__ wv,
                            const float* __restrict__ wg) {
    __shared__ float As[BM][BK + 1];
    __shared__ float Bs[BK][BN + 1];
    int tid = threadIdx.x;
    int tx = tid & 15, ty = tid >> 4;
    int m0 = blockIdx.y * BM;
    int n0 = blockIdx.x * BN;           // 0..511 in steps of 64
    int sel = n0 >> 7;                  // tile fully inside one weight matrix
    const float* W = (sel == 0) ? wq : (sel == 1) ? wk : (sel == 2) ? wv : wg;
    int ncol0 = n0 & 127;

    float acc[4][4] = {};
    for (int k0 = 0; k0 < CIN; k0 += BK) {
        #pragma unroll
        for (int e = 0; e < 8; e++) {
            int l = tid + 256 * e;
            As[l >> 5][l & 31] = g_zn[(m0 + (l >> 5)) * CIN + k0 + (l & 31)];
        }
        #pragma unroll
        for (int e = 0; e < 8; e++) {
            int l = tid + 256 * e;
            Bs[l >> 6][l & 63] = W[(k0 + (l >> 6)) * CIN + ncol0 + (l & 63)];
        }
        __syncthreads();
        #pragma unroll
        for (int kk = 0; kk < BK; kk++) {
            float ra[4], rb[4];
            #pragma unroll
            for (int ii = 0; ii < 4; ii++) ra[ii] = As[ty * 4 + ii][kk];
            #pragma unroll
            for (int jj = 0; jj < 4; jj++) rb[jj] = Bs[kk][tx * 4 + jj];
            #pragma unroll
            for (int ii = 0; ii < 4; ii++)
                #pragma unroll
                for (int jj = 0; jj < 4; jj++)
                    acc[ii][jj] += ra[ii] * rb[jj];
        }
        __syncthreads();
    }
    #pragma unroll
    for (int ii = 0; ii < 4; ii++)
        #pragma unroll
        for (int jj = 0; jj < 4; jj++) {
            int gm  = m0 + ty * 4 + ii;
            int lc  = ncol0 + tx * 4 + jj;   // 0..127 within matrix
            int idx = gm * CIN + lc;
            float val = acc[ii][jj];
            if      (sel == 0) g_q[idx] = val * QSCALE;
            else if (sel == 1) g_k[idx] = val;
            else if (sel == 2) g_v[idx] = val;
            else               g_g[idx] = 1.0f / (1.0f + __expf(-val));
        }
}

// ============================================================
// Kernel 3: attention per (i, h). 256 threads (8 warps).
// K stored transposed (c-major, row stride 385 -> conflict-free),
// q-vectors register-resident (4 rows/warp), probabilities staged
// per-warp in smem and read back as broadcast float4.
// ============================================================
constexpr int KTS = 385;                 // Kt row stride (odd -> no conflicts)
constexpr int ATT_THREADS = 256;

__global__ __launch_bounds__(ATT_THREADS, 1)
void attn_kernel(const float* __restrict__ mask) {
    int i = blockIdx.x, h = blockIdx.y;
    extern __shared__ float sm[];
    float* Kt = sm;                        // 32 * 385
    float* Vs = Kt + CHD * KTS;            // 384 * 32
    float* bs = Vs + NSEQ * CHD;           // 384
    float* ps = bs + NSEQ;                 // 8 warps * 4 * 384

    int tid = threadIdx.x, warp = tid >> 5, lane = tid & 31;

    // ---- load K (transposed) and V ----
    for (int l = tid; l < NSEQ * CHD; l += ATT_THREADS) {
        int k = l >> 5, c = l & 31;
        int gidx = ((i * NSEQ + k) * NH + h) * CHD + c;
        Kt[c * KTS + k] = g_k[gidx];       // write: lane=c -> stride 385, conflict-free
        Vs[k * CHD + c] = g_v[gidx];
    }
    for (int k = tid; k < NSEQ; k += ATT_THREADS)
        bs[k] = 1e9f * (mask[i * NSEQ + k] - 1.0f);
    __syncthreads();

    const float* trih = g_tri + h * NTOK;
    float* psw = ps + warp * 4 * NSEQ;

    // 12 passes: each pass, the 8 warps cover 32 q rows (4 per warp)
    for (int pass = 0; pass < 12; pass++) {
        int q0 = (pass * 8 + warp) * 4;

        // q rows for this warp -> registers (broadcast LDG.128, L1/L2 hits)
        float4 q4[4][8];
        #pragma unroll
        for (int qq = 0; qq < 4; qq++) {
            const float4* qp = (const float4*)&g_q[((i * NSEQ + q0 + qq) * NH + h) * CHD];
            #pragma unroll
            for (int c4 = 0; c4 < 8; c4++) q4[qq][c4] = qp[c4];
        }

        // ---- scores: S[4q][384k], lane owns k = kt*32+lane ----
        float s[4][12];
        float mx[4] = {-1e30f, -1e30f, -1e30f, -1e30f};
        #pragma unroll
        for (int kt = 0; kt < 12; kt++) {
            int k = kt * 32 + lane;
            float a[4] = {0.f, 0.f, 0.f, 0.f};
            #pragma unroll
            for (int c4 = 0; c4 < 8; c4++) {
                const float* kp = &Kt[(c4 * 4) * KTS + k];
                float k0 = kp[0], k1 = kp[KTS], k2 = kp[2 * KTS], k3 = kp[3 * KTS];
                #pragma unroll
                for (int qq = 0; qq < 4; qq++) {
                    a[qq] += q4[qq][c4].x * k0;
                    a[qq] += q4[qq][c4].y * k1;
                    a[qq] += q4[qq][c4].z * k2;
                    a[qq] += q4[qq][c4].w * k3;
                }
            }
            float bias = bs[k];
            #pragma unroll
            for (int qq = 0; qq < 4; qq++) {
                float sc = a[qq] + bias + trih[(q0 + qq) * NSEQ + k];
                s[qq][kt] = sc;
                mx[qq] = fmaxf(mx[qq], sc);
            }
        }

        // ---- softmax per q row ----
        #pragma unroll
        for (int qq = 0; qq < 4; qq++) {
            #pragma unroll
            for (int off = 16; off; off >>= 1)
                mx[qq] = fmaxf(mx[qq], __shfl_xor_sync(~0u, mx[qq], off));
        }
        float sum[4] = {0.f, 0.f, 0.f, 0.f};
        #pragma unroll
        for (int qq = 0; qq < 4; qq++)
            #pragma unroll
            for (int kt = 0; kt < 12; kt++) {
                float e = __expf(s[qq][kt] - mx[qq]);
                s[qq][kt] = e;
                sum[qq] += e;
            }
        #pragma unroll
        for (int qq = 0; qq < 4; qq++) {
            #pragma unroll
            for (int off = 16; off; off >>= 1)
                sum[qq] += __shfl_xor_sync(~0u, sum[qq], off);
            float inv = 1.0f / sum[qq];
            #pragma unroll
            for (int kt = 0; kt < 12; kt++)
                psw[qq * NSEQ + kt * 32 + lane] = s[qq][kt] * inv;
        }
        __syncwarp();

        // ---- AV: o[4q][c=lane] ----
        float o[4] = {0.f, 0.f, 0.f, 0.f};
        #pragma unroll 8
        for (int k4 = 0; k4 < NSEQ / 4; k4++) {
            int k = k4 * 4;
            float v0 = Vs[(k + 0) * CHD + lane];
            float v1 = Vs[(k + 1) * CHD + lane];
            float v2 = Vs[(k + 2) * CHD + lane];
            float v3 = Vs[(k + 3) * CHD + lane];
            #pragma unroll
            for (int qq = 0; qq < 4; qq++) {
                float4 p = *(const float4*)&psw[qq * NSEQ + k];  // broadcast
                o[qq] += p.x * v0;
                o[qq] += p.y * v1;
                o[qq] += p.z * v2;
                o[qq] += p.w * v3;
            }
        }
        #pragma unroll
        for (int qq = 0; qq < 4; qq++) {
            int idx = ((i * NSEQ + q0 + qq) * NH + h) * CHD + lane;
            g_og[idx] = o[qq] * g_g[idx];
        }
        __syncwarp();
    }
}

// ============================================================
// Kernel 4: out = og[NTOK,128] @ wo[128,128]
// ============================================================
__global__ void out_kernel(const float* __restrict__ wo,
                           float* __restrict__ out) {
    __shared__ float As[BM][BK + 1];
    __shared__ float Bs[BK][BN + 1];
    int tid = threadIdx.x;
    int tx = tid & 15, ty = tid >> 4;
    int m0 = blockIdx.y * BM;
    int n0 = blockIdx.x * BN;

    float acc[4][4] = {};
    for (int k0 = 0; k0 < CIN; k0 += BK) {
        #pragma unroll
        for (int e = 0; e < 8; e++) {
            int l = tid + 256 * e;
            As[l >> 5][l & 31] = g_og[(m0 + (l >> 5)) * CIN + k0 + (l & 31)];
        }
        #pragma unroll
        for (int e = 0; e < 8; e++) {
            int l = tid + 256 * e;
            Bs[l >> 6][l & 63] = wo[(k0 + (l >> 6)) * CIN + n0 + (l & 63)];
        }
        __syncthreads();
        #pragma unroll
        for (int kk = 0; kk < BK; kk++) {
            float ra[4], rb[4];
            #pragma unroll
            for (int ii = 0; ii < 4; ii++) ra[ii] = As[ty * 4 + ii][kk];
            #pragma unroll
            for (int jj = 0; jj < 4; jj++) rb[jj] = Bs[kk][tx * 4 + jj];
            #pragma unroll
            for (int ii = 0; ii < 4; ii++)
                #pragma unroll
                for (int jj = 0; jj < 4; jj++)
                    acc[ii][jj] += ra[ii] * rb[jj];
        }
        __syncthreads();
    }
    #pragma unroll
    for (int ii = 0; ii < 4; ii++)
        #pragma unroll
        for (int jj = 0; jj < 4; jj++)
            out[(m0 + ty * 4 + ii) * CIN + n0 + tx * 4 + jj] = acc[ii][jj];
}

// ============================================================
extern "C" void kernel_launch(void* const* d_in, const int* in_sizes, int n_in,
                              void* d_out, int out_size) {
    const float* z     = (const float*)d_in[0];
    const float* mask  = (const float*)d_in[1];
    const float* ln_w  = (const float*)d_in[2];
    const float* ln_b  = (const float*)d_in[3];
    const float* w_tri = (const float*)d_in[4];
    const float* wq    = (const float*)d_in[5];
    const float* wk    = (const float*)d_in[6];
    const float* wv    = (const float*)d_in[7];
    const float* wg    = (const float*)d_in[8];
    const float* wo    = (const float*)d_in[9];
    float* out = (float*)d_out;

    ln_tri_kernel<<<NTOK, 128>>>(z, ln_w, ln_b, w_tri);

    dim3 gp(512 / BN, NTOK / BM);
    proj_kernel<<<gp, 256>>>(wq, wk, wv, wg);

    size_t smem = (size_t)(CHD * KTS + NSEQ * CHD + NSEQ + 8 * 4 * NSEQ) * sizeof(float);
    cudaFuncSetAttribute(attn_kernel, cudaFuncAttributeMaxDynamicSharedMemorySize, (int)smem);
    dim3 ga(NSEQ, NH);
    attn_kernel<<<ga, ATT_THREADS, smem>>>(mask);

    dim3 go(CIN / BN, NTOK / BM);
    out_kernel<<<go, 256>>>(wo, out);
}

// round 3
// speedup vs baseline: 3.2613x; 2.0211x over previous
#include <cuda_runtime.h>
#include <math.h>
#include <stdint.h>

constexpr int NSEQ = 384;
constexpr int CIN  = 128;
constexpr int NH   = 4;
constexpr int CHD  = 32;
constexpr int NTOK = NSEQ * NSEQ;
constexpr float QSCALE = 0.17677669529663687f;

// ---- scratch ----
__device__ float g_zn[NTOK * CIN];
__device__ float g_q [NTOK * CIN];
__device__ float g_k [NTOK * CIN];
__device__ float g_v [NTOK * CIN];
__device__ float g_g [NTOK * CIN];
__device__ float g_og[NTOK * CIN];
__device__ float g_tri[NH * NTOK];   // [h][q*NSEQ+k]

__device__ __forceinline__ float to_tf32(float x) {
    float r; asm("cvt.rna.tf32.f32 %0, %1;" : "=f"(r) : "f"(x)); return r;
}
// D += A(16x8) * B(8x8), tf32
__device__ __forceinline__ void mma8(float* d, const uint32_t* a, const uint32_t* b) {
    asm volatile(
        "mma.sync.aligned.m16n8k8.row.col.f32.tf32.tf32.f32 "
        "{%0,%1,%2,%3},{%4,%5,%6,%7},{%8,%9},{%0,%1,%2,%3};"
        : "+f"(d[0]), "+f"(d[1]), "+f"(d[2]), "+f"(d[3])
        : "r"(a[0]), "r"(a[1]), "r"(a[2]), "r"(a[3]), "r"(b[0]), "r"(b[1]));
}

// ============================================================
// Kernel 1: LayerNorm + tri bias (unchanged)
// ============================================================
__global__ void ln_tri_kernel(const float* __restrict__ z,
                              const float* __restrict__ ln_w,
                              const float* __restrict__ ln_b,
                              const float* __restrict__ w_tri) {
    int t = blockIdx.x;
    int c = threadIdx.x;
    int lane = c & 31, warp = c >> 5;

    float x = z[t * CIN + c];
    float v1 = x, v2 = x * x;
    #pragma unroll
    for (int off = 16; off; off >>= 1) {
        v1 += __shfl_xor_sync(~0u, v1, off);
        v2 += __shfl_xor_sync(~0u, v2, off);
    }
    __shared__ float s1[4], s2[4];
    if (lane == 0) { s1[warp] = v1; s2[warp] = v2; }
    __syncthreads();
    float mean = (s1[0] + s1[1] + s1[2] + s1[3]) * (1.0f / CIN);
    float msq  = (s2[0] + s2[1] + s2[2] + s2[3]) * (1.0f / CIN);
    float var  = msq - mean * mean;
    float zn   = (x - mean) * rsqrtf(var + 1e-5f) * ln_w[c] + ln_b[c];
    g_zn[t * CIN + c] = zn;

    __shared__ float sh[4][4];
    float p[4];
    #pragma unroll
    for (int h = 0; h < 4; h++) p[h] = zn * w_tri[c * NH + h];
    #pragma unroll
    for (int off = 16; off; off >>= 1)
        #pragma unroll
        for (int h = 0; h < 4; h++) p[h] += __shfl_xor_sync(~0u, p[h], off);
    if (lane == 0)
        #pragma unroll
        for (int h = 0; h < 4; h++) sh[warp][h] = p[h];
    __syncthreads();
    if (c < 4)
        g_tri[c * NTOK + t] = sh[0][c] + sh[1][c] + sh[2][c] + sh[3][c];
}

// ============================================================
// Kernel 2: projections via tf32 mma. BM=128,BN=128,BK=128.
// A stride 132 (bank=4g+t), B stride 136 (bank=8t+g).
// ============================================================
constexpr int AS = 132, BS = 136;

__global__ __launch_bounds__(256, 1)
void proj_tc(const float* __restrict__ wq, const float* __restrict__ wk,
             const float* __restrict__ wv, const float* __restrict__ wg) {
    extern __shared__ float sm[];
    float* As = sm;              // 128 x AS
    float* Bs = sm + 128 * AS;   // 128 x BS
    int tid = threadIdx.x, lane = tid & 31, warp = tid >> 5;
    int g = lane >> 2, t = lane & 3;
    int sel = blockIdx.x;
    const float* W = (sel == 0) ? wq : (sel == 1) ? wk : (sel == 2) ? wv : wg;
    int m0 = blockIdx.y * 128;

    const float4* Ag = (const float4*)(g_zn + (size_t)m0 * CIN);
    const float4* Bg = (const float4*)W;
    #pragma unroll
    for (int e = 0; e < 16; e++) {
        int f = tid + e * 256;
        int row = f >> 5, c4 = (f & 31) * 4;
        float4 va = Ag[f];
        As[row * AS + c4 + 0] = to_tf32(va.x); As[row * AS + c4 + 1] = to_tf32(va.y);
        As[row * AS + c4 + 2] = to_tf32(va.z); As[row * AS + c4 + 3] = to_tf32(va.w);
        float4 vb = Bg[f];
        Bs[row * BS + c4 + 0] = to_tf32(vb.x); Bs[row * BS + c4 + 1] = to_tf32(vb.y);
        Bs[row * BS + c4 + 2] = to_tf32(vb.z); Bs[row * BS + c4 + 3] = to_tf32(vb.w);
    }
    __syncthreads();

    int wm = warp >> 1, wn = warp & 1;   // 4 x 2 warp grid; warp tile 32 x 64
    float acc[2][8][4] = {};
    #pragma unroll
    for (int kc = 0; kc < 16; kc++) {
        uint32_t a[2][4];
        #pragma unroll
        for (int mt = 0; mt < 2; mt++) {
            const uint32_t* ap = (const uint32_t*)(As + (wm * 32 + mt * 16 + g) * AS + kc * 8 + t);
            a[mt][0] = ap[0]; a[mt][1] = ap[8 * AS]; a[mt][2] = ap[4]; a[mt][3] = ap[8 * AS + 4];
        }
        #pragma unroll
        for (int nt = 0; nt < 8; nt++) {
            const uint32_t* bp = (const uint32_t*)(Bs + (kc * 8 + t) * BS + wn * 64 + nt * 8 + g);
            uint32_t b[2] = { bp[0], bp[4 * BS] };
            mma8(acc[0][nt], a[0], b);
            mma8(acc[1][nt], a[1], b);
        }
    }

    #pragma unroll
    for (int mt = 0; mt < 2; mt++)
        #pragma unroll
        for (int nt = 0; nt < 8; nt++)
            #pragma unroll
            for (int hf = 0; hf < 2; hf++) {
                int gm  = m0 + wm * 32 + mt * 16 + g + hf * 8;
                int col = wn * 64 + nt * 8 + 2 * t;
                float c0 = acc[mt][nt][hf * 2 + 0], c1 = acc[mt][nt][hf * 2 + 1];
                size_t idx = (size_t)gm * CIN + col;
                if (sel == 0) {
                    float2 o = { c0 * QSCALE, c1 * QSCALE };
                    *(float2*)&g_q[idx] = o;
                } else if (sel == 1) {
                    float2 o = { c0, c1 };
                    *(float2*)&g_k[idx] = o;
                } else if (sel == 2) {
                    float2 o = { c0, c1 };
                    *(float2*)&g_v[idx] = o;
                } else {
                    float2 o = { 1.0f / (1.0f + __expf(-c0)), 1.0f / (1.0f + __expf(-c1)) };
                    *(float2*)&g_g[idx] = o;
                }
            }
}

// ============================================================
// Kernel 3: attention via tf32 mma. Block = (i,h), 256 threads.
// 12 passes of 32 q-rows.
//   QK: warps 2(M) x 4(N), warp tile 16 x 96.
//   AV: warps 2(M) x 2(N) x 2(Ksplit), warp tile 16 x 16 x 192.
// ============================================================
constexpr int KS_S = 36, VS_S = 40, QS_S = 36, PS_S = 388, OB_S = 34;

__global__ __launch_bounds__(256, 1)
void attn_tc(const float* __restrict__ mask) {
    int i = blockIdx.x, h = blockIdx.y;
    extern __shared__ float sm[];
    float* Ks   = sm;                       // 384*36
    float* Vs   = Ks + NSEQ * KS_S;         // 384*40
    float* Qs   = Vs + NSEQ * VS_S;         // 32*36
    float* Ps   = Qs + 32 * QS_S;           // 32*388
    float* bsm  = Ps + 32 * PS_S;           // 384
    float* redA = bsm + NSEQ;               // 32*4
    float* redB = redA + 128;               // 32*4
    float* obuf = redB + 128;               // 32*34

    int tid = threadIdx.x, lane = tid & 31, warp = tid >> 5;
    int g = lane >> 2, t = lane & 3;

    // ---- load K, V (tf32) ----
    #pragma unroll
    for (int e = 0; e < 12; e++) {
        int f = tid + e * 256;                  // 3072 float4s
        int row = f >> 3, c4 = (f & 7) * 4;
        size_t src = (size_t)(i * NSEQ + row) * CIN + h * CHD + c4;
        float4 vk = *(const float4*)&g_k[src];
        Ks[row * KS_S + c4 + 0] = to_tf32(vk.x); Ks[row * KS_S + c4 + 1] = to_tf32(vk.y);
        Ks[row * KS_S + c4 + 2] = to_tf32(vk.z); Ks[row * KS_S + c4 + 3] = to_tf32(vk.w);
        float4 vv = *(const float4*)&g_v[src];
        Vs[row * VS_S + c4 + 0] = to_tf32(vv.x); Vs[row * VS_S + c4 + 1] = to_tf32(vv.y);
        Vs[row * VS_S + c4 + 2] = to_tf32(vv.z); Vs[row * VS_S + c4 + 3] = to_tf32(vv.w);
    }
    for (int k = tid; k < NSEQ; k += 256)
        bsm[k] = 1e9f * (mask[i * NSEQ + k] - 1.0f);
    __syncthreads();

    const float* trih = g_tri + (size_t)h * NTOK;
    int wm = warp & 1, wn = warp >> 1;                       // QK layout
    int wm2 = warp & 1, wn2 = (warp >> 1) & 1, wk2 = warp >> 2;  // AV layout

    for (int pass = 0; pass < 12; pass++) {
        int q0 = pass * 32;

        // ---- fill Qs (32x32, one float4 per thread) ----
        {
            int row = tid >> 3, c4 = (tid & 7) * 4;
            size_t src = (size_t)(i * NSEQ + q0 + row) * CIN + h * CHD + c4;
            float4 v = *(const float4*)&g_q[src];
            Qs[row * QS_S + c4 + 0] = to_tf32(v.x); Qs[row * QS_S + c4 + 1] = to_tf32(v.y);
            Qs[row * QS_S + c4 + 2] = to_tf32(v.z); Qs[row * QS_S + c4 + 3] = to_tf32(v.w);
        }
        __syncthreads();

        // ---- QK: S[16 x 96] per warp ----
        float s[12][4] = {};
        #pragma unroll
        for (int kc = 0; kc < 4; kc++) {
            const uint32_t* ap = (const uint32_t*)(Qs + (wm * 16 + g) * QS_S + kc * 8 + t);
            uint32_t a[4] = { ap[0], ap[8 * QS_S], ap[4], ap[8 * QS_S + 4] };
            #pragma unroll
            for (int nt = 0; nt < 12; nt++) {
                const uint32_t* bp = (const uint32_t*)(Ks + (wn * 96 + nt * 8 + g) * KS_S + kc * 8 + t);
                uint32_t b[2] = { bp[0], bp[4] };
                mma8(s[nt], a, b);
            }
        }

        // ---- biases + row max ----
        int qa = q0 + wm * 16 + g, qb = qa + 8;
        float rm0 = -1e30f, rm1 = -1e30f;
        #pragma unroll
        for (int nt = 0; nt < 12; nt++) {
            int k = wn * 96 + nt * 8 + 2 * t;
            float b0 = bsm[k], b1 = bsm[k + 1];
            float2 t0 = *(const float2*)&trih[(size_t)qa * NSEQ + k];
            float2 t1 = *(const float2*)&trih[(size_t)qb * NSEQ + k];
            s[nt][0] += b0 + t0.x; s[nt][1] += b1 + t0.y;
            s[nt][2] += b0 + t1.x; s[nt][3] += b1 + t1.y;
            rm0 = fmaxf(rm0, fmaxf(s[nt][0], s[nt][1]));
            rm1 = fmaxf(rm1, fmaxf(s[nt][2], s[nt][3]));
        }
        rm0 = fmaxf(rm0, __shfl_xor_sync(~0u, rm0, 1));
        rm0 = fmaxf(rm0, __shfl_xor_sync(~0u, rm0, 2));
        rm1 = fmaxf(rm1, __shfl_xor_sync(~0u, rm1, 1));
        rm1 = fmaxf(rm1, __shfl_xor_sync(~0u, rm1, 2));
        if (t == 0) {
            redA[(wm * 16 + g) * 4 + wn]     = rm0;
            redA[(wm * 16 + g + 8) * 4 + wn] = rm1;
        }
        __syncthreads();
        float4 r0 = *(const float4*)&redA[(wm * 16 + g) * 4];
        float4 r1 = *(const float4*)&redA[(wm * 16 + g + 8) * 4];
        float mx0 = fmaxf(fmaxf(r0.x, r0.y), fmaxf(r0.z, r0.w));
        float mx1 = fmaxf(fmaxf(r1.x, r1.y), fmaxf(r1.z, r1.w));

        // ---- exp + row sums ----
        float sum0 = 0.f, sum1 = 0.f;
        #pragma unroll
        for (int nt = 0; nt < 12; nt++) {
            s[nt][0] = __expf(s[nt][0] - mx0); sum0 += s[nt][0];
            s[nt][1] = __expf(s[nt][1] - mx0); sum0 += s[nt][1];
            s[nt][2] = __expf(s[nt][2] - mx1); sum1 += s[nt][2];
            s[nt][3] = __expf(s[nt][3] - mx1); sum1 += s[nt][3];
        }
        sum0 += __shfl_xor_sync(~0u, sum0, 1); sum0 += __shfl_xor_sync(~0u, sum0, 2);
        sum1 += __shfl_xor_sync(~0u, sum1, 1); sum1 += __shfl_xor_sync(~0u, sum1, 2);
        if (t == 0) {
            redB[(wm * 16 + g) * 4 + wn]     = sum0;
            redB[(wm * 16 + g + 8) * 4 + wn] = sum1;
        }
        __syncthreads();
        float4 u0 = *(const float4*)&redB[(wm * 16 + g) * 4];
        float4 u1 = *(const float4*)&redB[(wm * 16 + g + 8) * 4];
        float inv0 = 1.0f / (u0.x + u0.y + u0.z + u0.w);
        float inv1 = 1.0f / (u1.x + u1.y + u1.z + u1.w);

        // ---- store P (tf32) ----
        #pragma unroll
        for (int nt = 0; nt < 12; nt++) {
            int k = wn * 96 + nt * 8 + 2 * t;
            float2 p0 = { to_tf32(s[nt][0] * inv0), to_tf32(s[nt][1] * inv0) };
            *(float2*)&Ps[(wm * 16 + g) * PS_S + k] = p0;
            float2 p1 = { to_tf32(s[nt][2] * inv1), to_tf32(s[nt][3] * inv1) };
            *(float2*)&Ps[(wm * 16 + g + 8) * PS_S + k] = p1;
        }
        __syncthreads();

        // ---- AV: O[16 x 16] per warp, K split 2x192 ----
        float o[2][4] = {};
        #pragma unroll
        for (int kc = 0; kc < 24; kc++) {
            int kk = wk2 * 192 + kc * 8;
            const uint32_t* ap = (const uint32_t*)(Ps + (wm2 * 16 + g) * PS_S + kk + t);
            uint32_t a[4] = { ap[0], ap[8 * PS_S], ap[4], ap[8 * PS_S + 4] };
            #pragma unroll
            for (int nt = 0; nt < 2; nt++) {
                const uint32_t* bp = (const uint32_t*)(Vs + (kk + t) * VS_S + wn2 * 16 + nt * 8 + g);
                uint32_t b[2] = { bp[0], bp[4 * VS_S] };
                mma8(o[nt], a, b);
            }
        }
        if (wk2 == 1) {
            #pragma unroll
            for (int nt = 0; nt < 2; nt++) {
                int r = wm2 * 16 + g, c = wn2 * 16 + nt * 8 + 2 * t;
                float2 e0 = { o[nt][0], o[nt][1] };
                *(float2*)&obuf[r * OB_S + c] = e0;
                float2 e1 = { o[nt][2], o[nt][3] };
                *(float2*)&obuf[(r + 8) * OB_S + c] = e1;
            }
        }
        __syncthreads();
        if (wk2 == 0) {
            #pragma unroll
            for (int nt = 0; nt < 2; nt++) {
                int r = wm2 * 16 + g, c = wn2 * 16 + nt * 8 + 2 * t;
                float2 e0 = *(const float2*)&obuf[r * OB_S + c];
                float2 e1 = *(const float2*)&obuf[(r + 8) * OB_S + c];
                size_t idx0 = (size_t)(i * NSEQ + q0 + r) * CIN + h * CHD + c;
                size_t idx1 = idx0 + (size_t)8 * CIN;
                float2 gg0 = *(const float2*)&g_g[idx0];
                float2 gg1 = *(const float2*)&g_g[idx1];
                float2 w0 = { (o[nt][0] + e0.x) * gg0.x, (o[nt][1] + e0.y) * gg0.y };
                float2 w1 = { (o[nt][2] + e1.x) * gg1.x, (o[nt][3] + e1.y) * gg1.y };
                *(float2*)&g_og[idx0] = w0;
                *(float2*)&g_og[idx1] = w1;
            }
        }
        // next-pass Qs sync provides the ordering for obuf/Ps reuse
    }
}

// ============================================================
// Kernel 4: out = og @ wo via tf32 mma, BM=128,BN=128,BK=128
// ============================================================
__global__ __launch_bounds__(256, 1)
void out_tc(const float* __restrict__ wo, float* __restrict__ out) {
    extern __shared__ float sm[];
    float* As = sm;
    float* Bs = sm + 128 * AS;
    int tid = threadIdx.x, lane = tid & 31, warp = tid >> 5;
    int g = lane >> 2, t = lane & 3;
    int m0 = blockIdx.x * 128;

    const float4* Ag = (const float4*)(g_og + (size_t)m0 * CIN);
    const float4* Bg = (const float4*)wo;
    #pragma unroll
    for (int e = 0; e < 16; e++) {
        int f = tid + e * 256;
        int row = f >> 5, c4 = (f & 31) * 4;
        float4 va = Ag[f];
        As[row * AS + c4 + 0] = to_tf32(va.x); As[row * AS + c4 + 1] = to_tf32(va.y);
        As[row * AS + c4 + 2] = to_tf32(va.z); As[row * AS + c4 + 3] = to_tf32(va.w);
        float4 vb = Bg[f];
        Bs[row * BS + c4 + 0] = to_tf32(vb.x); Bs[row * BS + c4 + 1] = to_tf32(vb.y);
        Bs[row * BS + c4 + 2] = to_tf32(vb.z); Bs[row * BS + c4 + 3] = to_tf32(vb.w);
    }
    __syncthreads();

    int wm = warp >> 1, wn = warp & 1;
    float acc[2][8][4] = {};
    #pragma unroll
    for (int kc = 0; kc < 16; kc++) {
        uint32_t a[2][4];
        #pragma unroll
        for (int mt = 0; mt < 2; mt++) {
            const uint32_t* ap = (const uint32_t*)(As + (wm * 32 + mt * 16 + g) * AS + kc * 8 + t);
            a[mt][0] = ap[0]; a[mt][1] = ap[8 * AS]; a[mt][2] = ap[4]; a[mt][3] = ap[8 * AS + 4];
        }
        #pragma unroll
        for (int nt = 0; nt < 8; nt++) {
            const uint32_t* bp = (const uint32_t*)(Bs + (kc * 8 + t) * BS + wn * 64 + nt * 8 + g);
            uint32_t b[2] = { bp[0], bp[4 * BS] };
            mma8(acc[0][nt], a[0], b);
            mma8(acc[1][nt], a[1], b);
        }
    }
    #pragma unroll
    for (int mt = 0; mt < 2; mt++)
        #pragma unroll
        for (int nt = 0; nt < 8; nt++)
            #pragma unroll
            for (int hf = 0; hf < 2; hf++) {
                int gm  = m0 + wm * 32 + mt * 16 + g + hf * 8;
                int col = wn * 64 + nt * 8 + 2 * t;
                float2 o = { acc[mt][nt][hf * 2 + 0], acc[mt][nt][hf * 2 + 1] };
                *(float2*)&out[(size_t)gm * CIN + col] = o;
            }
}

// ============================================================
extern "C" void kernel_launch(void* const* d_in, const int* in_sizes, int n_in,
                              void* d_out, int out_size) {
    const float* z     = (const float*)d_in[0];
    const float* mask  = (const float*)d_in[1];
    const float* ln_w  = (const float*)d_in[2];
    const float* ln_b  = (const float*)d_in[3];
    const float* w_tri = (const float*)d_in[4];
    const float* wq    = (const float*)d_in[5];
    const float* wk    = (const float*)d_in[6];
    const float* wv    = (const float*)d_in[7];
    const float* wg    = (const float*)d_in[8];
    const float* wo    = (const float*)d_in[9];
    float* out = (float*)d_out;

    ln_tri_kernel<<<NTOK, 128>>>(z, ln_w, ln_b, w_tri);

    size_t gemm_smem = (size_t)(128 * AS + 128 * BS) * sizeof(float);  // 137216
    cudaFuncSetAttribute(proj_tc, cudaFuncAttributeMaxDynamicSharedMemorySize, (int)gemm_smem);
    cudaFuncSetAttribute(out_tc,  cudaFuncAttributeMaxDynamicSharedMemorySize, (int)gemm_smem);

    dim3 gp(4, NTOK / 128);
    proj_tc<<<gp, 256, gemm_smem>>>(wq, wk, wv, wg);

    size_t att_smem = (size_t)(NSEQ * KS_S + NSEQ * VS_S + 32 * QS_S + 32 * PS_S
                               + NSEQ + 128 + 128 + 32 * OB_S) * sizeof(float);  // ~177.9KB
    cudaFuncSetAttribute(attn_tc, cudaFuncAttributeMaxDynamicSharedMemorySize, (int)att_smem);
    dim3 ga(NSEQ, NH);
    attn_tc<<<ga, 256, att_smem>>>(mask);

    out_tc<<<NTOK / 128, 256, gemm_smem>>>(wo, out);
}